// round 2
// baseline (speedup 1.0000x reference)
#include <cuda_runtime.h>
#include <cstdint>

#define NN   50000
#define TT   12
#define FIN  128
#define NH   4
#define DD   128
#define EE   800000
#define ETOT 850000      // EE + NN self-loops
#define G3   384
#define WS_STRIDE 386    // padded [k][j] smem stride (386 % 32 == 2 -> conflict-light, even -> float2-aligned)

// ---------------- scratch (device globals: allocation-free rule) ----------------
__device__ float    d_g  [(size_t)TT * NN * DD];   // GAT aggregated output (pre-bias/relu), [T][N][128]
__device__ float    d_gi [(size_t)TT * NN * G3];   // gi = relu(g+b_gat) @ W_ih^T + b_ih
__device__ float    d_h  [(size_t)NN * DD];        // per-t GAT features h
__device__ float    d_als[NN * NH];
__device__ float    d_ald[NN * NH];
__device__ unsigned d_mkey[NN * NH];               // segment-max keys (order-preserving uint)
__device__ float    d_den[NN * NH];
__device__ float    d_e  [(size_t)ETOT * NH];      // edge logits -> unnormalized weights
__device__ float    d_hs [(size_t)NN * DD];        // GRU hidden state

// ---------------- helpers ----------------
__device__ __forceinline__ void ffma2(float2 &c, float2 a, float2 b) {
    asm("fma.rn.f32x2 %0, %1, %2, %0;"
        : "+l"(reinterpret_cast<unsigned long long&>(c))
        : "l"(reinterpret_cast<const unsigned long long&>(a)),
          "l"(reinterpret_cast<const unsigned long long&>(b)));
}

__device__ __forceinline__ void red_add_v4(float* addr, float4 v) {
    asm volatile("red.global.add.v4.f32 [%0], {%1,%2,%3,%4};"
                 :: "l"(addr), "f"(v.x), "f"(v.y), "f"(v.z), "f"(v.w) : "memory");
}

__device__ __forceinline__ unsigned f2ord(float f) {
    unsigned u = __float_as_uint(f);
    return (u & 0x80000000u) ? ~u : (u | 0x80000000u);
}
__device__ __forceinline__ float ord2f(unsigned k) {
    return (k & 0x80000000u) ? __uint_as_float(k & 0x7FFFFFFFu) : __uint_as_float(~k);
}

__device__ __forceinline__ float sigm(float x)   { return __fdividef(1.f, 1.f + __expf(-x)); }
__device__ __forceinline__ float tanh_f(float x) { return 1.f - __fdividef(2.f, __expf(2.f * x) + 1.f); }

// ---------------- init / zero kernels ----------------
__global__ void k_zero_hs() {
    int i = blockIdx.x * 256 + threadIdx.x;          // over NN*DD/4 = 1.6M float4
    if (i < NN * DD / 4) ((float4*)d_hs)[i] = make_float4(0.f, 0.f, 0.f, 0.f);
}

__global__ void k_zero_t(int t) {
    int i = blockIdx.x * 256 + threadIdx.x;
    if (i < NN * DD / 4)
        ((float4*)(d_g + (size_t)t * NN * DD))[i] = make_float4(0.f, 0.f, 0.f, 0.f);
    if (i < NN * NH / 4) {
        ((uint4*)d_mkey)[i] = make_uint4(0u, 0u, 0u, 0u);   // key 0 == below every real value
        ((float4*)d_den)[i] = make_float4(0.f, 0.f, 0.f, 0.f);
    }
}

// ---------------- GAT feature GEMM: d_h = x_t @ W_gat ----------------
__global__ void __launch_bounds__(256) k_gat_gemm(const float* __restrict__ x,
                                                  const float* __restrict__ Wg, int t) {
    extern __shared__ float sm[];
    float* Ws = sm;           // [128][128], k-major (same as input layout)
    float* Xs = sm + 16384;   // [64][128]
    int tid = threadIdx.x;
    int row0 = blockIdx.x * 64;

    for (int i = tid; i < 4096; i += 256)
        ((float4*)Ws)[i] = ((const float4*)Wg)[i];
    for (int i = tid; i < 2048; i += 256) {
        int r = i >> 5, c4 = i & 31;
        int gr = row0 + r;
        float4 v = make_float4(0.f, 0.f, 0.f, 0.f);
        if (gr < NN) v = ((const float4*)(x + ((size_t)gr * TT + t) * FIN))[c4];
        ((float4*)Xs)[i] = v;
    }
    __syncthreads();

    int tx = tid & 31, ty = tid >> 5;
    float2 acc[8][2];
#pragma unroll
    for (int i = 0; i < 8; i++) { acc[i][0] = make_float2(0.f, 0.f); acc[i][1] = make_float2(0.f, 0.f); }

    for (int k = 0; k < 128; k += 4) {
        float4 xv[8];
#pragma unroll
        for (int i = 0; i < 8; i++) xv[i] = *(const float4*)&Xs[(ty + 8 * i) * 128 + k];
#pragma unroll
        for (int kk = 0; kk < 4; kk++) {
            float4 wv = *(const float4*)&Ws[(k + kk) * 128 + tx * 4];
            float2 w0 = make_float2(wv.x, wv.y), w1 = make_float2(wv.z, wv.w);
#pragma unroll
            for (int i = 0; i < 8; i++) {
                float xs = (kk == 0) ? xv[i].x : (kk == 1) ? xv[i].y : (kk == 2) ? xv[i].z : xv[i].w;
                float2 xp = make_float2(xs, xs);
                ffma2(acc[i][0], xp, w0);
                ffma2(acc[i][1], xp, w1);
            }
        }
    }
#pragma unroll
    for (int i = 0; i < 8; i++) {
        int gr = row0 + ty + 8 * i;
        if (gr < NN)
            *(float4*)&d_h[(size_t)gr * DD + tx * 4] =
                make_float4(acc[i][0].x, acc[i][0].y, acc[i][1].x, acc[i][1].y);
    }
}

// ---------------- per-node attention logits ----------------
__global__ void k_al(const float* __restrict__ a_src, const float* __restrict__ a_dst) {
    int i = blockIdx.x * 256 + threadIdx.x;   // over N*H
    if (i >= NN * NH) return;
    int n = i >> 2, h = i & 3;
    const float4* hp = (const float4*)&d_h[(size_t)n * DD + h * 32];
    const float4* as = (const float4*)&a_src[h * 32];
    const float4* ad = (const float4*)&a_dst[h * 32];
    float ss = 0.f, sd = 0.f;
#pragma unroll
    for (int j = 0; j < 8; j++) {
        float4 hv = hp[j], av = as[j], dv = ad[j];
        ss += hv.x * av.x + hv.y * av.y + hv.z * av.z + hv.w * av.w;
        sd += hv.x * dv.x + hv.y * dv.y + hv.z * dv.z + hv.w * dv.w;
    }
    d_als[i] = ss;
    d_ald[i] = sd;
}

// ---------------- attention pass 1: logits + segment max ----------------
__global__ void k_att1(const int* __restrict__ src, const int* __restrict__ dst) {
    int i = blockIdx.x * 256 + threadIdx.x;
    if (i >= ETOT) return;
    int s, d;
    if (i < EE) { s = __ldg(src + i); d = __ldg(dst + i); } else { s = d = i - EE; }
    float4 as = *(const float4*)&d_als[s * 4];
    float4 ad = *(const float4*)&d_ald[d * 4];
    float4 e;
    e.x = as.x + ad.x; e.x = e.x > 0.f ? e.x : 0.2f * e.x;
    e.y = as.y + ad.y; e.y = e.y > 0.f ? e.y : 0.2f * e.y;
    e.z = as.z + ad.z; e.z = e.z > 0.f ? e.z : 0.2f * e.z;
    e.w = as.w + ad.w; e.w = e.w > 0.f ? e.w : 0.2f * e.w;
    *(float4*)&d_e[(size_t)i * 4] = e;
    atomicMax(d_mkey + d * 4 + 0, f2ord(e.x));
    atomicMax(d_mkey + d * 4 + 1, f2ord(e.y));
    atomicMax(d_mkey + d * 4 + 2, f2ord(e.z));
    atomicMax(d_mkey + d * 4 + 3, f2ord(e.w));
}

// ---------------- attention pass 2: exp + segment sum ----------------
__global__ void k_att2(const int* __restrict__ dst) {
    int i = blockIdx.x * 256 + threadIdx.x;
    if (i >= ETOT) return;
    int d = (i < EE) ? __ldg(dst + i) : (i - EE);
    float4 e = *(const float4*)&d_e[(size_t)i * 4];
    uint4 mk = *(const uint4*)&d_mkey[d * 4];
    float4 w;
    w.x = __expf(e.x - ord2f(mk.x));
    w.y = __expf(e.y - ord2f(mk.y));
    w.z = __expf(e.z - ord2f(mk.z));
    w.w = __expf(e.w - ord2f(mk.w));
    *(float4*)&d_e[(size_t)i * 4] = w;
    red_add_v4(d_den + d * 4, w);
}

// ---------------- attention pass 3: weighted message scatter (1 warp / edge) ----------------
__global__ void __launch_bounds__(256) k_att3(const int* __restrict__ src,
                                              const int* __restrict__ dst, int t) {
    int gw   = (blockIdx.x * 256 + threadIdx.x) >> 5;
    int lane = threadIdx.x & 31;
    if (gw >= ETOT) return;
    int s, d;
    if (gw < EE) { s = __ldg(src + gw); d = __ldg(dst + gw); } else { s = d = gw - EE; }
    int head = lane >> 3;                          // lane*4 .. lane*4+3 all inside one head
    float wgt = d_e[(size_t)gw * 4 + head];
    float den = d_den[d * 4 + head];
    float alpha = wgt / (den + 1e-16f);
    float4 hv = ((const float4*)(d_h + (size_t)s * DD))[lane];
    float4 msg = make_float4(hv.x * alpha, hv.y * alpha, hv.z * alpha, hv.w * alpha);
    red_add_v4(d_g + ((size_t)t * NN + d) * DD + lane * 4, msg);
}

// ---------------- gi GEMM (batched over all T): gi = relu(g + b_gat) @ W_ih^T + b_ih ----------------
__global__ void __launch_bounds__(256) k_gi_gemm(const float* __restrict__ Wih,
                                                 const float* __restrict__ bih,
                                                 const float* __restrict__ bg) {
    extern __shared__ float sm[];
    float* Ws = sm;                         // [128][386] transposed W_ih (k-major)
    float* Xs = sm + 128 * WS_STRIDE;       // [64][128]
    int tid = threadIdx.x;
    size_t row0 = (size_t)blockIdx.x * 64;  // flat row over T*N = 600000 (exact multiple of 64)

    for (int i = tid; i < G3 * 128; i += 256) {
        int j = i >> 7, k = i & 127;
        Ws[k * WS_STRIDE + j] = Wih[i];
    }
    for (int i = tid; i < 2048; i += 256) {
        int r = i >> 5, c4 = i & 31;
        float4 g = ((const float4*)(d_g + (row0 + r) * DD))[c4];
        float4 b = ((const float4*)bg)[c4];
        float4 v;
        v.x = fmaxf(g.x + b.x, 0.f); v.y = fmaxf(g.y + b.y, 0.f);
        v.z = fmaxf(g.z + b.z, 0.f); v.w = fmaxf(g.w + b.w, 0.f);
        ((float4*)Xs)[i] = v;
    }
    __syncthreads();

    int tx = tid & 31, ty = tid >> 5;
    float2 acc[8][6];
#pragma unroll
    for (int i = 0; i < 8; i++)
#pragma unroll
        for (int m = 0; m < 6; m++) acc[i][m] = make_float2(0.f, 0.f);

    for (int k = 0; k < 128; k += 4) {
        float4 xv[8];
#pragma unroll
        for (int i = 0; i < 8; i++) xv[i] = *(const float4*)&Xs[(ty + 8 * i) * 128 + k];
#pragma unroll
        for (int kk = 0; kk < 4; kk++) {
            const float* wb = &Ws[(k + kk) * WS_STRIDE + tx * 4];
            float2 w0 = *(const float2*)(wb);
            float2 w1 = *(const float2*)(wb + 2);
            float2 w2 = *(const float2*)(wb + 128);
            float2 w3 = *(const float2*)(wb + 130);
            float2 w4 = *(const float2*)(wb + 256);
            float2 w5 = *(const float2*)(wb + 258);
#pragma unroll
            for (int i = 0; i < 8; i++) {
                float xs = (kk == 0) ? xv[i].x : (kk == 1) ? xv[i].y : (kk == 2) ? xv[i].z : xv[i].w;
                float2 xp = make_float2(xs, xs);
                ffma2(acc[i][0], xp, w0); ffma2(acc[i][1], xp, w1);
                ffma2(acc[i][2], xp, w2); ffma2(acc[i][3], xp, w3);
                ffma2(acc[i][4], xp, w4); ffma2(acc[i][5], xp, w5);
            }
        }
    }
    float4 b0 = *(const float4*)&bih[tx * 4];
    float4 b1 = *(const float4*)&bih[128 + tx * 4];
    float4 b2 = *(const float4*)&bih[256 + tx * 4];
#pragma unroll
    for (int i = 0; i < 8; i++) {
        size_t gr = row0 + ty + 8 * i;
        float* o = d_gi + gr * G3;
        *(float4*)(o + tx * 4)       = make_float4(acc[i][0].x + b0.x, acc[i][0].y + b0.y,
                                                   acc[i][1].x + b0.z, acc[i][1].y + b0.w);
        *(float4*)(o + 128 + tx * 4) = make_float4(acc[i][2].x + b1.x, acc[i][2].y + b1.y,
                                                   acc[i][3].x + b1.z, acc[i][3].y + b1.w);
        *(float4*)(o + 256 + tx * 4) = make_float4(acc[i][4].x + b2.x, acc[i][4].y + b2.y,
                                                   acc[i][5].x + b2.z, acc[i][5].y + b2.w);
    }
}

// ---------------- GRU step: gh = h @ W_hh^T + b_hh; gate math; h update (in-place) ----------------
__global__ void __launch_bounds__(256) k_gru(int t, const float* __restrict__ Whh,
                                             const float* __restrict__ bhh) {
    extern __shared__ float sm[];
    float* Ws = sm;                       // [128][386] transposed W_hh
    float* Xs = sm + 128 * WS_STRIDE;     // [64][128] h tile
    int tid = threadIdx.x;
    int row0 = blockIdx.x * 64;

    for (int i = tid; i < G3 * 128; i += 256) {
        int j = i >> 7, k = i & 127;
        Ws[k * WS_STRIDE + j] = Whh[i];
    }
    for (int i = tid; i < 2048; i += 256) {
        int r = i >> 5, c4 = i & 31;
        int gr = row0 + r;
        float4 v = make_float4(0.f, 0.f, 0.f, 0.f);
        if (gr < NN) v = ((const float4*)(d_hs + (size_t)gr * DD))[c4];
        ((float4*)Xs)[i] = v;
    }
    __syncthreads();

    int tx = tid & 31, ty = tid >> 5;
    float2 acc[8][6];
#pragma unroll
    for (int i = 0; i < 8; i++)
#pragma unroll
        for (int m = 0; m < 6; m++) acc[i][m] = make_float2(0.f, 0.f);

    for (int k = 0; k < 128; k += 4) {
        float4 xv[8];
#pragma unroll
        for (int i = 0; i < 8; i++) xv[i] = *(const float4*)&Xs[(ty + 8 * i) * 128 + k];
#pragma unroll
        for (int kk = 0; kk < 4; kk++) {
            const float* wb = &Ws[(k + kk) * WS_STRIDE + tx * 4];
            float2 w0 = *(const float2*)(wb);
            float2 w1 = *(const float2*)(wb + 2);
            float2 w2 = *(const float2*)(wb + 128);
            float2 w3 = *(const float2*)(wb + 130);
            float2 w4 = *(const float2*)(wb + 256);
            float2 w5 = *(const float2*)(wb + 258);
#pragma unroll
            for (int i = 0; i < 8; i++) {
                float xs = (kk == 0) ? xv[i].x : (kk == 1) ? xv[i].y : (kk == 2) ? xv[i].z : xv[i].w;
                float2 xp = make_float2(xs, xs);
                ffma2(acc[i][0], xp, w0); ffma2(acc[i][1], xp, w1);
                ffma2(acc[i][2], xp, w2); ffma2(acc[i][3], xp, w3);
                ffma2(acc[i][4], xp, w4); ffma2(acc[i][5], xp, w5);
            }
        }
    }
    float4 br = *(const float4*)&bhh[tx * 4];
    float4 bz = *(const float4*)&bhh[128 + tx * 4];
    float4 bn = *(const float4*)&bhh[256 + tx * 4];
#pragma unroll
    for (int i = 0; i < 8; i++) {
        int gr = row0 + ty + 8 * i;
        if (gr >= NN) continue;
        const float* gp = d_gi + ((size_t)t * NN + gr) * G3;
        float4 gir = *(const float4*)(gp + tx * 4);
        float4 giz = *(const float4*)(gp + 128 + tx * 4);
        float4 gin = *(const float4*)(gp + 256 + tx * 4);
        float4 ghr = make_float4(acc[i][0].x + br.x, acc[i][0].y + br.y,
                                 acc[i][1].x + br.z, acc[i][1].y + br.w);
        float4 ghz = make_float4(acc[i][2].x + bz.x, acc[i][2].y + bz.y,
                                 acc[i][3].x + bz.z, acc[i][3].y + bz.w);
        float4 ghn = make_float4(acc[i][4].x + bn.x, acc[i][4].y + bn.y,
                                 acc[i][5].x + bn.z, acc[i][5].y + bn.w);
        float4 hold = *(const float4*)&Xs[(ty + 8 * i) * 128 + tx * 4];
        float4 hn;
        {
            float r = sigm(gir.x + ghr.x), z = sigm(giz.x + ghz.x);
            float n = tanh_f(gin.x + r * ghn.x);
            hn.x = (1.f - z) * n + z * hold.x;
        }
        {
            float r = sigm(gir.y + ghr.y), z = sigm(giz.y + ghz.y);
            float n = tanh_f(gin.y + r * ghn.y);
            hn.y = (1.f - z) * n + z * hold.y;
        }
        {
            float r = sigm(gir.z + ghr.z), z = sigm(giz.z + ghz.z);
            float n = tanh_f(gin.z + r * ghn.z);
            hn.z = (1.f - z) * n + z * hold.z;
        }
        {
            float r = sigm(gir.w + ghr.w), z = sigm(giz.w + ghz.w);
            float n = tanh_f(gin.w + r * ghn.w);
            hn.w = (1.f - z) * n + z * hold.w;
        }
        *(float4*)&d_hs[(size_t)gr * DD + tx * 4] = hn;
    }
}

// ---------------- final linear ----------------
__global__ void k_final(const float* __restrict__ Wlin, const float* __restrict__ blin,
                        float* __restrict__ out) {
    int gw   = (blockIdx.x * 256 + threadIdx.x) >> 5;
    int lane = threadIdx.x & 31;
    if (gw >= NN) return;
    float4 h = ((const float4*)(d_hs + (size_t)gw * DD))[lane];
    float4 w = ((const float4*)Wlin)[lane];
    float v = h.x * w.x + h.y * w.y + h.z * w.z + h.w * w.w;
#pragma unroll
    for (int o = 16; o > 0; o >>= 1) v += __shfl_xor_sync(0xFFFFFFFFu, v, o);
    if (lane == 0) out[gw] = v + __ldg(blin);
}

// ---------------- launch ----------------
extern "C" void kernel_launch(void* const* d_in, const int* in_sizes, int n_in,
                              void* d_out, int out_size) {
    const float* x   = (const float*)d_in[0];
    const int*   ei  = (const int*)  d_in[1];
    const float* Wg  = (const float*)d_in[2];
    const float* a_s = (const float*)d_in[3];
    const float* a_d = (const float*)d_in[4];
    const float* b_g = (const float*)d_in[5];
    const float* Wih = (const float*)d_in[6];
    const float* Whh = (const float*)d_in[7];
    const float* bih = (const float*)d_in[8];
    const float* bhh = (const float*)d_in[9];
    const float* Wl  = (const float*)d_in[10];
    const float* bl  = (const float*)d_in[11];
    float* out = (float*)d_out;

    cudaFuncSetAttribute(k_gat_gemm, cudaFuncAttributeMaxDynamicSharedMemorySize, 98304);
    cudaFuncSetAttribute(k_gi_gemm,  cudaFuncAttributeMaxDynamicSharedMemorySize, 230400);
    cudaFuncSetAttribute(k_gru,      cudaFuncAttributeMaxDynamicSharedMemorySize, 230400);

    k_zero_hs<<<6250, 256>>>();

    for (int t = 0; t < TT; t++) {
        const int* src = ei + (size_t)t * 2 * EE;
        const int* dst = src + EE;
        k_zero_t<<<6250, 256>>>(t);
        k_gat_gemm<<<782, 256, 98304>>>(x, Wg, t);
        k_al<<<782, 256>>>(a_s, a_d);
        k_att1<<<3321, 256>>>(src, dst);
        k_att2<<<3321, 256>>>(dst);
        k_att3<<<106250, 256>>>(src, dst, t);
    }

    k_gi_gemm<<<9375, 256, 230400>>>(Wih, bih, b_g);
    for (int t = 0; t < TT; t++)
        k_gru<<<782, 256, 230400>>>(t, Whh, bhh);

    k_final<<<6250, 256>>>(Wl, bl, out);
}